// round 4
// baseline (speedup 1.0000x reference)
#include <cuda_runtime.h>
#include <cuda_bf16.h>
#include <cstdint>

// out = tanh( Xa @ W1'^T + T[b] ),  T = s @ W2^T,  s[b] = sum_a x[b,a,:]
// W1' = Wh - Wc/7, W2 = Wc/7.  Split-bf16 HMMA, fp32 staging via cp.async.
// Tile: 128 agent rows (16 batch rows). 8 warps: (g = w>>1) row groups
// {16g, 16g+64} x (c = w&1) 32-col halves of W1'; plus each warp owns an
// 8-col slice of T (= s @ W2^T).

#define NTILES 4096

#define OFF_WH 0
#define OFF_WL 16384
#define OFF_XH 32768
#define OFF_XL 49152
#define OFF_SH 65536
#define OFF_SL 67584
#define OFF_T  69632
#define TSTRIDE 68
#define OFF_F  74240
#define SMEM_BYTES 107008

__device__ __forceinline__ uint32_t smem_u32(const void* p) {
    uint32_t a;
    asm("{ .reg .u64 t; cvta.to.shared.u64 t, %1; cvt.u32.u64 %0, t; }"
        : "=r"(a) : "l"(p));
    return a;
}

__device__ __forceinline__ uint32_t pack_bf16(float a, float b) {
    __nv_bfloat162 t = __float22bfloat162_rn(make_float2(a, b));
    return *reinterpret_cast<uint32_t*>(&t);
}

__device__ __forceinline__ void mma_bf16(float* c, const uint32_t* a,
                                         uint32_t b0, uint32_t b1) {
    asm volatile(
        "mma.sync.aligned.m16n8k16.row.col.f32.bf16.bf16.f32 "
        "{%0,%1,%2,%3}, {%4,%5,%6,%7}, {%8,%9}, {%0,%1,%2,%3};"
        : "+f"(c[0]), "+f"(c[1]), "+f"(c[2]), "+f"(c[3])
        : "r"(a[0]), "r"(a[1]), "r"(a[2]), "r"(a[3]), "r"(b0), "r"(b1));
}

__device__ __forceinline__ void ldsm4(uint32_t* r, uint32_t addr) {
    asm volatile(
        "ldmatrix.sync.aligned.m8n8.x4.shared.b16 {%0,%1,%2,%3}, [%4];"
        : "=r"(r[0]), "=r"(r[1]), "=r"(r[2]), "=r"(r[3]) : "r"(addr));
}

__device__ __forceinline__ void ldsm2(uint32_t* r, uint32_t addr) {
    asm volatile(
        "ldmatrix.sync.aligned.m8n8.x2.shared.b16 {%0,%1}, [%2];"
        : "=r"(r[0]), "=r"(r[1]) : "r"(addr));
}

__device__ __forceinline__ float tanh_fast(float y) {
    float r;
    asm("tanh.approx.f32 %0, %1;" : "=f"(r) : "f"(y));
    return r;
}

// Stage one 128-row tile of fp32 x into the smem fstage via cp.async.
__device__ __forceinline__ void stage_tile(uint32_t fbase, const float* x,
                                           int t, int b8, int dc) {
    const float* src = x + (size_t)t * 8192 + (size_t)b8 * 64 + dc * 4;
    uint32_t dst = fbase + b8 * 256 + dc * 16;
#pragma unroll
    for (int a = 0; a < 8; a++) {
        asm volatile("cp.async.ca.shared.global [%0], [%1], 16;"
                     :: "r"(dst + a * 256), "l"(src + (size_t)a * 64)
                     : "memory");
    }
    asm volatile("cp.async.commit_group;" ::: "memory");
}

__global__ void __launch_bounds__(256, 2)
comm_hmma2(const float* __restrict__ x, const float* __restrict__ Wh,
           const float* __restrict__ Wc, float* __restrict__ out) {
    extern __shared__ char smem[];
    const uint32_t sb = smem_u32(smem);

    const int tid = threadIdx.x;
    const int w = tid >> 5;
    const int lane = tid & 31;
    const int g = w >> 1;       // row group 0..3
    const int c = w & 1;        // 32-col half of W1'
    const int b16 = tid >> 4;   // batch row 0..15 (staging role)
    const int dc = tid & 15;    // 16B d-chunk    (staging role)
    const int b8 = b16 << 3;

    int t = blockIdx.x;
    const int stride = gridDim.x;

    // kick off staging of first tile
    stage_tile(sb + OFF_F, x, t, b8, dc);

    // ---- Build W tiles in smem: rows 0-63 = W1' = Wh - Wc/7; 64-127 = Wc/7
    for (int j = tid; j < 8192; j += 256) {
        int n = j >> 6, d = j & 63;
        float cc = Wc[((n & 63) << 6) + d] * (1.0f / 7.0f);
        float wv = (n < 64) ? (Wh[(n << 6) + d] - cc) : cc;
        __nv_bfloat16 h = __float2bfloat16(wv);
        __nv_bfloat16 l = __float2bfloat16(wv - __bfloat162float(h));
        uint32_t off = (n << 7) + ((((d >> 3) ^ (n & 7)) << 4)) + ((d & 7) << 1);
        *(__nv_bfloat16*)(smem + OFF_WH + off) = h;
        *(__nv_bfloat16*)(smem + OFF_WL + off) = l;
    }
    __syncthreads();

    // ---- per-warp invariant addresses ----
    const int arow = lane & 15, ahi = lane >> 4, arow7 = arow & 7;
    // B-frag rows for W1 slice (cols 32c..32c+31 across 4 nb)
    const int browW1 = (c << 5) + lane;
    const uint32_t bbW1 = (uint32_t)(browW1 << 7);
    const int b7W1 = browW1 & 7;
    // B-frag rows for this warp's W2 8-col slice
    const int brow2 = 64 + (w << 3) + (lane & 7);
    const int g2 = (lane >> 3) & 1;
    const uint32_t bb2 = (uint32_t)(brow2 << 7);
    const int b72 = brow2 & 7;

    // ---- W1h B fragments resident in registers: bW[ks][granule][nb] ----
    uint32_t bW[4][2][4];
#pragma unroll
    for (int ks = 0; ks < 4; ks++) {
#pragma unroll
        for (int gk = 0; gk < 2; gk++) {
            uint32_t addr =
                sb + OFF_WH + bbW1 + ((((2 * ks + gk) ^ b7W1)) << 4);
            ldsm4(bW[ks][gk], addr);
        }
    }

    float* Tp = (float*)(smem + OFF_T);

    for (;;) {
        // ---- wait staged fp32, convert to split-bf16, compute s ----
        asm volatile("cp.async.wait_group 0;" ::: "memory");
        {
            float4 sv = make_float4(0.f, 0.f, 0.f, 0.f);
            const char* fp = smem + OFF_F + b8 * 256 + dc * 16;
            uint32_t xoff =
                ((((dc >> 1)) << 4)) + ((dc & 1) << 3);  // granule+8B (pre-XOR)
#pragma unroll
            for (int a = 0; a < 8; a++) {
                float4 v = *(const float4*)(fp + a * 256);
                sv.x += v.x; sv.y += v.y; sv.z += v.z; sv.w += v.w;
                float h0 = __bfloat162float(__float2bfloat16(v.x));
                float h1 = __bfloat162float(__float2bfloat16(v.y));
                float h2 = __bfloat162float(__float2bfloat16(v.z));
                float h3 = __bfloat162float(__float2bfloat16(v.w));
                uint2 hv = make_uint2(pack_bf16(h0, h1), pack_bf16(h2, h3));
                uint2 lv = make_uint2(pack_bf16(v.x - h0, v.y - h1),
                                      pack_bf16(v.z - h2, v.w - h3));
                int r = b8 + a;
                uint32_t ro = (uint32_t)(r << 7) +
                              (((((dc >> 1) ^ (r & 7))) << 4)) + ((dc & 1) << 3);
                *(uint2*)(smem + OFF_XH + ro) = hv;
                *(uint2*)(smem + OFF_XL + ro) = lv;
            }
            float sh0 = __bfloat162float(__float2bfloat16(sv.x));
            float sh1 = __bfloat162float(__float2bfloat16(sv.y));
            float sh2 = __bfloat162float(__float2bfloat16(sv.z));
            float sh3 = __bfloat162float(__float2bfloat16(sv.w));
            uint32_t so = (uint32_t)(b16 << 7) +
                          (((((dc >> 1) ^ (b16 & 7))) << 4)) + ((dc & 1) << 3);
            *(uint2*)(smem + OFF_SH + so) =
                make_uint2(pack_bf16(sh0, sh1), pack_bf16(sh2, sh3));
            *(uint2*)(smem + OFF_SL + so) =
                make_uint2(pack_bf16(sv.x - sh0, sv.y - sh1),
                           pack_bf16(sv.z - sh2, sv.w - sh3));
            (void)xoff;
        }
        __syncthreads();

        int tn = t + stride;
        bool more = (tn < NTILES);
        if (more) stage_tile(sb + OFF_F, x, tn, b8, dc);  // overlaps MMA

        // ---- T GEMM: this warp's 8-col slice of s @ W2^T ----
        {
            float accT[4] = {0.f, 0.f, 0.f, 0.f};
#pragma unroll
            for (int ks = 0; ks < 4; ks++) {
                uint32_t sa = (uint32_t)(arow << 7) +
                              ((((2 * ks + ahi) ^ arow7)) << 4);
                uint32_t b2a = bb2 + ((((2 * ks + g2) ^ b72)) << 4);
                uint32_t sh_[4], sl_[4], b2h[2], b2l[2];
                ldsm4(sh_, sb + OFF_SH + sa);
                ldsm2(b2h, sb + OFF_WH + b2a);
                mma_bf16(accT, sh_, b2h[0], b2h[1]);
                ldsm2(b2l, sb + OFF_WL + b2a);
                mma_bf16(accT, sh_, b2l[0], b2l[1]);
                ldsm4(sl_, sb + OFF_SL + sa);
                mma_bf16(accT, sl_, b2h[0], b2h[1]);
            }
            int tr = lane >> 2, tcx = (w << 3) + ((lane & 3) << 1);
            *(float2*)(Tp + tr * TSTRIDE + tcx) = make_float2(accT[0], accT[1]);
            *(float2*)(Tp + (tr + 8) * TSTRIDE + tcx) =
                make_float2(accT[2], accT[3]);
        }

        // ---- Y1 GEMM: rows {16g, 16g+64}, cols 32c..32c+31, 3 splits ----
        float accY[2][4][4] = {};
#pragma unroll
        for (int ks = 0; ks < 4; ks++) {
            uint32_t bl0[4], bl1[4];
            ldsm4(bl0, sb + OFF_WL + bbW1 + ((((2 * ks) ^ b7W1)) << 4));
            ldsm4(bl1, sb + OFF_WL + bbW1 + ((((2 * ks + 1) ^ b7W1)) << 4));
#pragma unroll
            for (int bt = 0; bt < 2; bt++) {
                int rb = (g << 4) + (bt << 6);
                uint32_t xa = (uint32_t)((rb + arow) << 7) +
                              ((((2 * ks + ahi) ^ arow7)) << 4);
                uint32_t ah[4], al[4];
                ldsm4(ah, sb + OFF_XH + xa);
#pragma unroll
                for (int nb = 0; nb < 4; nb++)
                    mma_bf16(accY[bt][nb], ah, bW[ks][0][nb], bW[ks][1][nb]);
#pragma unroll
                for (int nb = 0; nb < 4; nb++)
                    mma_bf16(accY[bt][nb], ah, bl0[nb], bl1[nb]);
                ldsm4(al, sb + OFF_XL + xa);
#pragma unroll
                for (int nb = 0; nb < 4; nb++)
                    mma_bf16(accY[bt][nb], al, bW[ks][0][nb], bW[ks][1][nb]);
            }
        }
        __syncthreads();

        // ---- epilogue: add T, tanh, store ----
#pragma unroll
        for (int bt = 0; bt < 2; bt++) {
#pragma unroll
            for (int h = 0; h < 2; h++) {
                int bb = 2 * g + 8 * bt + h;
                const float* Trow =
                    Tp + bb * TSTRIDE + (c << 5) + ((lane & 3) << 1);
                int R = t * 128 + (g << 4) + (bt << 6) + (h << 3) + (lane >> 2);
                float* op = out + (size_t)R * 64 + (c << 5) + ((lane & 3) << 1);
#pragma unroll
                for (int nb = 0; nb < 4; nb++) {
                    float2 tv = *(const float2*)(Trow + (nb << 3));
                    float y0 = accY[bt][nb][2 * h] + tv.x;
                    float y1 = accY[bt][nb][2 * h + 1] + tv.y;
                    *(float2*)(op + (nb << 3)) =
                        make_float2(tanh_fast(y0), tanh_fast(y1));
                }
            }
        }

        if (!more) break;
        t = tn;
    }
}

extern "C" void kernel_launch(void* const* d_in, const int* in_sizes, int n_in,
                              void* d_out, int out_size) {
    const float* x  = (const float*)d_in[0];
    const float* Wh = (const float*)d_in[1];
    const float* Wc = (const float*)d_in[2];
    float* out = (float*)d_out;

    int dev = 0, sms = 148;
    cudaGetDevice(&dev);
    cudaDeviceGetAttribute(&sms, cudaDevAttrMultiProcessorCount, dev);

    cudaFuncSetAttribute(comm_hmma2,
                         cudaFuncAttributeMaxDynamicSharedMemorySize,
                         SMEM_BYTES);
    comm_hmma2<<<2 * sms, 256, SMEM_BYTES>>>(x, Wh, Wc, out);
}